// round 4
// baseline (speedup 1.0000x reference)
#include <cuda_runtime.h>
#include <cuda_bf16.h>

// RoiPoolingLayer: image (1,128,128,512) fp32 NHWC, RoI (1000,4) fp32 [cx,cy,w,h]
// out (1,1000,7,7,512) fp32.
//
// Grid: blockIdx.y = roi (1000), blockIdx.x = pooled point py*7+px (49).
// Block: 128 threads, one float4 (4 channels) per thread (512 channels total).
// Each block blends 4 source pixels' channel vectors with bilinear weights.

#define H_IMG 128
#define W_IMG 128
#define C_IMG 512
#define POOL 7
#define NROI 1000
#define STRIDE_F 16.0f

__device__ __forceinline__ void axis_coords(float start, float size, int p, int limit,
                                            int& i0, int& i1, float& frac) {
    // matches _axis_coords: half-pixel bilinear resize coords, fp32 throughout
    float grid = ((float)p + 0.5f) / (float)POOL;
    float s = grid * size - 0.5f;
    s = fminf(fmaxf(s, 0.0f), size - 1.0f);
    float f0 = floorf(s);
    frac = s - f0;
    float f1 = fminf(f0 + 1.0f, size - 1.0f);
    float lim = (float)(limit - 1);
    i0 = (int)fminf(fmaxf(start + f0, 0.0f), lim);
    i1 = (int)fminf(fmaxf(start + f1, 0.0f), lim);
}

__global__ __launch_bounds__(128) void roi_pool_kernel(
    const float* __restrict__ feat,   // [128,128,512]
    const float* __restrict__ roi,    // [1000,4]
    float* __restrict__ out)          // [1000,7,7,512]
{
    const int p  = blockIdx.x;        // 0..48
    const int n  = blockIdx.y;        // 0..999
    const int py = p / POOL;
    const int px = p % POOL;

    // Per-RoI quantized window (uniform across block; cheap scalar math)
    const float x = roi[n * 4 + 0];
    const float y = roi[n * 4 + 1];
    const float w = roi[n * 4 + 2];
    const float h = roi[n * 4 + 3];

    // jnp.round == round-half-to-even == rintf under default rounding mode
    const float r  = rintf((x - w * 0.5f) / STRIDE_F);
    const float c  = rintf((y - h * 0.5f) / STRIDE_F);
    const float wq = fmaxf(rintf(w / STRIDE_F), 1.0f);
    const float hq = fmaxf(rintf(h / STRIDE_F), 1.0f);

    int iy0, iy1, ix0, ix1;
    float ly, lx;
    axis_coords(c, hq, py, H_IMG, iy0, iy1, ly);   // y axis uses (c, hq), limit H
    axis_coords(r, wq, px, W_IMG, ix0, ix1, lx);   // x axis uses (r, wq), limit W

    const float w00 = (1.0f - ly) * (1.0f - lx);
    const float w01 = (1.0f - ly) * lx;
    const float w10 = ly * (1.0f - lx);
    const float w11 = ly * lx;

    // float4 channel index for this thread
    const int t = threadIdx.x;                      // 0..127
    const float4* __restrict__ f4 = (const float4*)feat;
    float4* __restrict__ o4 = (float4*)out;

    const int b00 = (iy0 * W_IMG + ix0) * (C_IMG / 4);
    const int b01 = (iy0 * W_IMG + ix1) * (C_IMG / 4);
    const int b10 = (iy1 * W_IMG + ix0) * (C_IMG / 4);
    const int b11 = (iy1 * W_IMG + ix1) * (C_IMG / 4);

    const float4 v00 = f4[b00 + t];
    const float4 v01 = f4[b01 + t];
    const float4 v10 = f4[b10 + t];
    const float4 v11 = f4[b11 + t];

    float4 o;
    o.x = w00 * v00.x + w01 * v01.x + w10 * v10.x + w11 * v11.x;
    o.y = w00 * v00.y + w01 * v01.y + w10 * v10.y + w11 * v11.y;
    o.z = w00 * v00.z + w01 * v01.z + w10 * v10.z + w11 * v11.z;
    o.w = w00 * v00.w + w01 * v01.w + w10 * v10.w + w11 * v11.w;

    o4[(size_t)(n * (POOL * POOL) + p) * (C_IMG / 4) + t] = o;
}

extern "C" void kernel_launch(void* const* d_in, const int* in_sizes, int n_in,
                              void* d_out, int out_size) {
    const float* image = (const float*)d_in[0];   // 1*128*128*512
    const float* roi   = (const float*)d_in[1];   // 1000*4
    float* out = (float*)d_out;                   // 1*1000*7*7*512

    dim3 grid(POOL * POOL, NROI);
    roi_pool_kernel<<<grid, 128>>>(image, roi, out);
}